// round 6
// baseline (speedup 1.0000x reference)
#include <cuda_runtime.h>
#include <math.h>

#define POOL 7
#define ROI_SCALE 0.0625f
#define WPB 8        // warps per block
#define CH  4        // channels per warp
#define CMW 66       // smem row pitch (64 cols + 2 pad, even for STS.64)

// Warp task = (roi, channel-group of 4, row-bin half: bins 0-3 / 4-6).
// Wide ROIs (x-window > 32 cols): lanes = 64 x-columns via float2, 1 row-pair
//   unrolled per iter.
// Narrow ROIs (x-window <= 32 cols, the common case): 2D lanes — lanes 0-15
//   cover 32 cols of even rows, lanes 16-31 odd rows -> 2 rows/iter (4 with
//   unroll), all lanes productive. Parities merged with shfl_xor(16).
// Each bin flushes column maxima to 1KB/warp smem; lanes 0..27 = (ch,pw) do
// the x-direction segmented max and write the output bin.
__global__ __launch_bounds__(32 * WPB, 5)
void roipool_kernel(const float* __restrict__ feat,
                    const float* __restrict__ rois,
                    float* __restrict__ out,
                    int N, int C, int write_bid) {
    __shared__ float cm[WPB][CH * CMW];
    const int H = 64, W = 64;

    int warp = threadIdx.x >> 5;
    int lane = threadIdx.x & 31;
    int NG = C / CH;
    int w = blockIdx.x * WPB + warp;

    // Fused second output of the reference tuple: batch ids as floats.
    if (write_bid && blockIdx.x == 0 && threadIdx.x < N) {
        out[(size_t)N * C * POOL * POOL + threadIdx.x] =
            (float)((int)rois[threadIdx.x * 5]);
    }
    if (w >= N * NG * 2) return;
    int n    = w / (NG * 2);
    int rem  = w - n * (NG * 2);
    int cg   = rem >> 1;
    int half = rem & 1;
    int ph_lo = half ? 4 : 0;
    int ph_hi = half ? (POOL - 1) : 3;

    const float* r = rois + n * 5;
    int b  = (int)r[0];
    // jnp.round = round-half-to-even = __float2int_rn
    int px = __float2int_rn(r[1] * ROI_SCALE);
    int py = __float2int_rn(r[2] * ROI_SCALE);
    int qx = __float2int_rn(r[3] * ROI_SCALE);
    int qy = __float2int_rn(r[4] * ROI_SCALE);

    int lenx = max(qx - px + 1, 1);
    int leny = max(qy - py + 1, 1);
    int psx  = (lenx + POOL - 1) / POOL;
    int psy  = (leny + POOL - 1) / POOL;
    int pad0x = (psx * POOL - lenx) / 2;
    int pad0y = (psy * POOL - leny) / 2;

    int px2 = px & ~1;                           // even-aligned load base
    int dpx = px - px2;                          // 0 or 1
    bool narrow = (qx - px2) < 32;               // whole x-window in 32 cols

    const float2* plane2 = (const float2*)(feat
        + (size_t)(b * C + cg * CH) * H * W + py * W + px2);
    const int PLANE2 = H * W / 2;                // plane stride in float2

    // wide-mode lane config: lane = float2 column index
    bool act_w = (px2 + 2 * lane) <= qx;
    const float2* bw = plane2 + lane;
    // narrow-mode lane config: (row parity, float2 column)
    int lanec = lane & 15;
    int lanehalf = lane >> 4;
    bool act_n = (px2 + 2 * lanec) <= qx;
    const float2* bn = plane2 + lanec + lanehalf * (W / 2);

    float* cw = cm[warp];

    // Fixed reduce role for lanes 0..27: (rch, rpw)
    int rch = lane / POOL;                       // 0..3 (lane<28)
    int rpw = lane - rch * POOL;                 // 0..6
    bool red = lane < CH * POOL;
    int x0 = rpw * psx - pad0x;
    int i0 = max(0, -x0);
    int i1 = min(psx, lenx - x0);
    bool padx = (rpw * psx < pad0x) | ((rpw + 1) * psx > pad0x + lenx);
    const float* rp = cw + rch * CMW + x0 + dpx;
    size_t obase = (size_t)(n * C + cg * CH) * POOL * POOL
                 + (size_t)rch * POOL * POOL + rpw;

#define FM2(d, s) d.x = fmaxf(d.x, s.x); d.y = fmaxf(d.y, s.y)
#define LOAD4(p, t0, t1, t2, t3) \
    t0 = __ldg(p); t1 = __ldg((p) + PLANE2); \
    t2 = __ldg((p) + 2 * PLANE2); t3 = __ldg((p) + 3 * PLANE2)

    for (int ph = ph_lo; ph <= ph_hi; ++ph) {
        int ys = max(0, ph * psy - pad0y);
        int ye = min(leny - 1, (ph + 1) * psy - 1 - pad0y);

        float2 a0 = make_float2(-INFINITY, -INFINITY);
        float2 a1 = a0, a2 = a0, a3 = a0;

        if (narrow) {
            const float2* p = bn + ys * (W / 2);
            int ry = ys;
            for (; ry + 3 <= ye; ry += 4) {       // 4 rows / iter
                if (act_n) {
                    float2 u0, u1, u2, u3, v0, v1, v2, v3;
                    LOAD4(p, u0, u1, u2, u3);
                    LOAD4(p + W, v0, v1, v2, v3);
                    FM2(u0, v0); FM2(u1, v1); FM2(u2, v2); FM2(u3, v3);
                    FM2(a0, u0); FM2(a1, u1); FM2(a2, u2); FM2(a3, u3);
                }
                p += 2 * W;
            }
            for (; ry + 1 <= ye; ry += 2) {       // 2 rows / iter
                if (act_n) {
                    float2 v0, v1, v2, v3;
                    LOAD4(p, v0, v1, v2, v3);
                    FM2(a0, v0); FM2(a1, v1); FM2(a2, v2); FM2(a3, v3);
                }
                p += W;
            }
            if (ry <= ye && act_n && lanehalf == 0) {  // leftover single row
                float2 v0, v1, v2, v3;
                LOAD4(p, v0, v1, v2, v3);
                FM2(a0, v0); FM2(a1, v1); FM2(a2, v2); FM2(a3, v3);
            }
            // merge row parities: lane L <-> L^16 hold the same columns
            a0.x = fmaxf(a0.x, __shfl_xor_sync(0xffffffffu, a0.x, 16));
            a0.y = fmaxf(a0.y, __shfl_xor_sync(0xffffffffu, a0.y, 16));
            a1.x = fmaxf(a1.x, __shfl_xor_sync(0xffffffffu, a1.x, 16));
            a1.y = fmaxf(a1.y, __shfl_xor_sync(0xffffffffu, a1.y, 16));
            a2.x = fmaxf(a2.x, __shfl_xor_sync(0xffffffffu, a2.x, 16));
            a2.y = fmaxf(a2.y, __shfl_xor_sync(0xffffffffu, a2.y, 16));
            a3.x = fmaxf(a3.x, __shfl_xor_sync(0xffffffffu, a3.x, 16));
            a3.y = fmaxf(a3.y, __shfl_xor_sync(0xffffffffu, a3.y, 16));
            if (lanehalf == 0) {                 // lanes 0-15 flush 32 cols
                int si = 2 * lanec;
                *(float2*)(cw + 0 * CMW + si) = a0;
                *(float2*)(cw + 1 * CMW + si) = a1;
                *(float2*)(cw + 2 * CMW + si) = a2;
                *(float2*)(cw + 3 * CMW + si) = a3;
            }
        } else {
            const float2* p = bw + ys * (W / 2);
            int ry = ys;
            for (; ry + 1 <= ye; ry += 2) {       // 2 rows / iter
                if (act_w) {
                    float2 u0, u1, u2, u3, v0, v1, v2, v3;
                    LOAD4(p, u0, u1, u2, u3);
                    LOAD4(p + W / 2, v0, v1, v2, v3);
                    FM2(u0, v0); FM2(u1, v1); FM2(u2, v2); FM2(u3, v3);
                    FM2(a0, u0); FM2(a1, u1); FM2(a2, u2); FM2(a3, u3);
                }
                p += W;
            }
            if (ry <= ye && act_w) {
                float2 v0, v1, v2, v3;
                LOAD4(p, v0, v1, v2, v3);
                FM2(a0, v0); FM2(a1, v1); FM2(a2, v2); FM2(a3, v3);
            }
            int si = 2 * lane;
            *(float2*)(cw + 0 * CMW + si) = a0;
            *(float2*)(cw + 1 * CMW + si) = a1;
            *(float2*)(cw + 2 * CMW + si) = a2;
            *(float2*)(cw + 3 * CMW + si) = a3;
        }
        __syncwarp();
        if (red) {
            float mm = -INFINITY;
            for (int i = i0; i < i1; ++i) mm = fmaxf(mm, rp[i]);
            bool pady = (ph * psy < pad0y) | ((ph + 1) * psy > pad0y + leny);
            if (padx | pady) mm = fmaxf(mm, 0.0f);
            if (!isfinite(mm)) mm = 0.0f;        // fully-padded bin -> 0
            out[obase + ph * POOL] = mm;
        }
        __syncwarp();
    }
#undef FM2
#undef LOAD4
}

extern "C" void kernel_launch(void* const* d_in, const int* in_sizes, int n_in,
                              void* d_out, int out_size) {
    const float* feat = (const float*)d_in[0];
    const float* rois = (const float*)d_in[1];
    float* out = (float*)d_out;

    const int C = 256;
    int N = in_sizes[1] / 5;

    int total = N * C * POOL * POOL;
    int write_bid = (out_size >= total + N) ? 1 : 0;

    int nwarps = N * (C / CH) * 2;
    int blocks = (nwarps + WPB - 1) / WPB;
    roipool_kernel<<<blocks, 32 * WPB>>>(feat, rois, out, N, C, write_bid);
}

// round 8
// speedup vs baseline: 1.0960x; 1.0960x over previous
#include <cuda_runtime.h>
#include <math.h>

#define POOL 7
#define ROI_SCALE 0.0625f
#define WPB 8        // warps per block
#define CH  4        // channels per warp
#define NG  64       // channel groups = C/CH
#define CMW 66       // smem row pitch (64 cols + 2 pad, even for STS.64)
#define TPR (NG * POOL)   // warp-tasks per ROI: 64 channel-groups x 7 row-bins

// grid = (TPR/WPB, N). Block owns one ROI: thread 0 decodes the ROI geometry
// once into smem (rounding + all integer divisions), then each warp handles
// one (channel-group of 4, row-bin) task: accumulate column maxima over the
// bin's rows (float2 loads, 64 x-cols/warp, 2 rows unrolled -> 8 LDG.64 in
// flight), flush to 1KB/warp smem, lanes 0..27 = (ch,pw) do the x-direction
// segmented max and write the 28 outputs of this bin.
__global__ __launch_bounds__(32 * WPB, 5)
void roipool_kernel(const float* __restrict__ feat,
                    const float* __restrict__ rois,
                    float* __restrict__ out,
                    int N, int C, int write_bid) {
    __shared__ float cm[WPB][CH * CMW];
    __shared__ int g[10];   // b,px,py,qx, lenx,leny, psx,psy, pad0x,pad0y
    const int H = 64, W = 64;

    int n = blockIdx.y;

    // Fused second output of the reference tuple: batch ids as floats.
    if (write_bid && blockIdx.x == 0 && blockIdx.y == 0 && threadIdx.x < N) {
        out[(size_t)N * C * POOL * POOL + threadIdx.x] =
            (float)((int)rois[threadIdx.x * 5]);
    }

    if (threadIdx.x == 0) {
        const float* r = rois + n * 5;
        // jnp.round = round-half-to-even = __float2int_rn
        int px = __float2int_rn(r[1] * ROI_SCALE);
        int py = __float2int_rn(r[2] * ROI_SCALE);
        int qx = __float2int_rn(r[3] * ROI_SCALE);
        int qy = __float2int_rn(r[4] * ROI_SCALE);
        int lenx = max(qx - px + 1, 1);
        int leny = max(qy - py + 1, 1);
        int psx  = (lenx + POOL - 1) / POOL;
        int psy  = (leny + POOL - 1) / POOL;
        g[0] = (int)r[0];
        g[1] = px; g[2] = py; g[3] = qx;
        g[4] = lenx; g[5] = leny;
        g[6] = psx; g[7] = psy;
        g[8] = (psx * POOL - lenx) / 2;
        g[9] = (psy * POOL - leny) / 2;
    }
    __syncthreads();

    int warp = threadIdx.x >> 5;
    int lane = threadIdx.x & 31;
    int task = blockIdx.x * WPB + warp;   // 0..TPR-1
    int cg   = task & 63;                 // channel group (4 channels), 0..63
    int ph   = task >> 6;                 // row bin 0..6

    int b = g[0], px = g[1], py = g[2], qx = g[3];
    int lenx = g[4], leny = g[5], psx = g[6], psy = g[7];
    int pad0x = g[8], pad0y = g[9];

    // Fixed reduce role for lanes 0..27: (rch, rpw)
    int rch = lane / POOL;                // 0..3 (lane<28), const div -> mul
    int rpw = lane - rch * POOL;          // 0..6
    bool red = lane < CH * POOL;
    size_t obase = (size_t)(n * C + cg * CH) * POOL * POOL
                 + (size_t)rch * POOL * POOL + (size_t)ph * POOL + rpw;

    // rows of this bin (ROI-relative), clipped to the real crop
    int ys = max(0, ph * psy - pad0y);
    int ye = min(leny - 1, (ph + 1) * psy - 1 - pad0y);

    if (ys > ye) {                        // fully zero-padded row bin -> 0
        if (red) out[obase] = 0.0f;
        return;
    }

    int px2 = px & ~1;                    // even-aligned load base
    int dpx = px - px2;                   // 0 or 1
    bool act = (px2 + 2 * lane) <= qx;    // this lane's float2 needed?

    const float2* p = (const float2*)(feat
        + (size_t)(b * C + cg * CH) * H * W + (py + ys) * W + px2) + lane;
    const int PLANE2 = H * W / 2;         // plane stride in float2

    float2 a0 = make_float2(-INFINITY, -INFINITY);
    float2 a1 = a0, a2 = a0, a3 = a0;

#define FM2(d, s) d.x = fmaxf(d.x, s.x); d.y = fmaxf(d.y, s.y)
#define LOAD4(q, t0, t1, t2, t3) \
    t0 = __ldg(q); t1 = __ldg((q) + PLANE2); \
    t2 = __ldg((q) + 2 * PLANE2); t3 = __ldg((q) + 3 * PLANE2)

    int ry = ys;
    for (; ry + 1 <= ye; ry += 2) {       // 2 rows / iter, 8 LDG in flight
        if (act) {
            float2 u0, u1, u2, u3, v0, v1, v2, v3;
            LOAD4(p, u0, u1, u2, u3);
            LOAD4(p + W / 2, v0, v1, v2, v3);
            FM2(u0, v0); FM2(u1, v1); FM2(u2, v2); FM2(u3, v3);
            FM2(a0, u0); FM2(a1, u1); FM2(a2, u2); FM2(a3, u3);
        }
        p += W;
    }
    if (ry <= ye && act) {
        float2 v0, v1, v2, v3;
        LOAD4(p, v0, v1, v2, v3);
        FM2(a0, v0); FM2(a1, v1); FM2(a2, v2); FM2(a3, v3);
    }
#undef FM2
#undef LOAD4

    // flush column maxima and reduce x-direction
    float* cw = cm[warp];
    int si = 2 * lane;
    *(float2*)(cw + 0 * CMW + si) = a0;
    *(float2*)(cw + 1 * CMW + si) = a1;
    *(float2*)(cw + 2 * CMW + si) = a2;
    *(float2*)(cw + 3 * CMW + si) = a3;
    __syncwarp();
    if (red) {
        int x0 = rpw * psx - pad0x;
        int i0 = max(0, -x0);
        int i1 = min(psx, lenx - x0);
        const float* rp = cw + rch * CMW + x0 + dpx;
        float mm = -INFINITY;
        for (int i = i0; i < i1; ++i) mm = fmaxf(mm, rp[i]);
        bool padx = (rpw * psx < pad0x) | ((rpw + 1) * psx > pad0x + lenx);
        bool pady = (ph * psy < pad0y) | ((ph + 1) * psy > pad0y + leny);
        if (padx | pady) mm = fmaxf(mm, 0.0f);
        if (!isfinite(mm)) mm = 0.0f;     // fully-padded bin -> 0
        out[obase] = mm;
    }
}

extern "C" void kernel_launch(void* const* d_in, const int* in_sizes, int n_in,
                              void* d_out, int out_size) {
    const float* feat = (const float*)d_in[0];
    const float* rois = (const float*)d_in[1];
    float* out = (float*)d_out;

    const int C = 256;
    int N = in_sizes[1] / 5;

    int total = N * C * POOL * POOL;
    int write_bid = (out_size >= total + N) ? 1 : 0;

    dim3 grid(TPR / WPB, N);              // 56 x N blocks
    roipool_kernel<<<grid, 32 * WPB>>>(feat, rois, out, N, C, write_bid);
}

// round 9
// speedup vs baseline: 1.2166x; 1.1100x over previous
#include <cuda_runtime.h>
#include <math.h>

#define POOL 7
#define ROI_SCALE 0.0625f
#define WPB 8        // warps per block
#define CH  8        // channels per warp
#define NGR 32       // channel groups = C/CH
#define CMW 66       // smem row pitch (64 cols + 2 pad, even for STS.64)
#define TPR (NGR * POOL)  // warp-tasks per ROI: 32 groups x 7 row-bins = 224

// grid = (TPR/WPB, N) = (28, N). Block owns one ROI: thread 0 decodes the ROI
// geometry once into smem, then each warp handles one (channel-group of 8,
// row-bin) task: accumulate column maxima over the bin's rows (float2 loads,
// 64 x-cols/warp, 8 planes -> 8 LDG.64 in flight per row), flush to 2KB/warp
// smem, each lane reduces 2 of the 56 (ch,pw) outputs via the x-direction
// segmented max.
__global__ __launch_bounds__(32 * WPB, 4)
void roipool_kernel(const float* __restrict__ feat,
                    const float* __restrict__ rois,
                    float* __restrict__ out,
                    int N, int C, int write_bid) {
    __shared__ float cm[WPB][CH * CMW];
    __shared__ int g[10];   // b,px,py,qx, lenx,leny, psx,psy, pad0x,pad0y
    const int H = 64, W = 64;

    int n = blockIdx.y;

    // Fused second output of the reference tuple: batch ids as floats.
    if (write_bid && blockIdx.x == 0 && blockIdx.y == 0 && threadIdx.x < N) {
        out[(size_t)N * C * POOL * POOL + threadIdx.x] =
            (float)((int)rois[threadIdx.x * 5]);
    }

    if (threadIdx.x == 0) {
        const float* r = rois + n * 5;
        // jnp.round = round-half-to-even = __float2int_rn
        int px = __float2int_rn(r[1] * ROI_SCALE);
        int py = __float2int_rn(r[2] * ROI_SCALE);
        int qx = __float2int_rn(r[3] * ROI_SCALE);
        int qy = __float2int_rn(r[4] * ROI_SCALE);
        int lenx = max(qx - px + 1, 1);
        int leny = max(qy - py + 1, 1);
        int psx  = (lenx + POOL - 1) / POOL;   // const-div -> mul
        int psy  = (leny + POOL - 1) / POOL;
        g[0] = (int)r[0];
        g[1] = px; g[2] = py; g[3] = qx;
        g[4] = lenx; g[5] = leny;
        g[6] = psx; g[7] = psy;
        g[8] = (psx * POOL - lenx) / 2;
        g[9] = (psy * POOL - leny) / 2;
    }
    __syncthreads();

    int warp = threadIdx.x >> 5;
    int lane = threadIdx.x & 31;
    int task = blockIdx.x * WPB + warp;   // 0..TPR-1
    int cg   = task & (NGR - 1);          // channel group (8 channels)
    int ph   = task >> 5;                 // row bin 0..6

    int b = g[0], px = g[1], py = g[2], qx = g[3];
    int lenx = g[4], leny = g[5], psx = g[6], psy = g[7];
    int pad0x = g[8], pad0y = g[9];

    // rows of this bin (ROI-relative), clipped to the real crop
    int ys = max(0, ph * psy - pad0y);
    int ye = min(leny - 1, (ph + 1) * psy - 1 - pad0y);

    // Each lane owns 2 of the CH*POOL = 56 (ch,pw) outputs: lane and lane+32.
    int bi0 = lane;
    int bi1 = lane + 32;
    int ch0 = bi0 / POOL, pw0 = bi0 - ch0 * POOL;   // const-div
    int ch1 = bi1 / POOL, pw1 = bi1 - ch1 * POOL;
    bool r1 = bi1 < CH * POOL;
    size_t ob = (size_t)(n * C + cg * CH) * POOL * POOL + (size_t)ph * POOL;
    size_t o0 = ob + (size_t)ch0 * POOL * POOL + pw0;
    size_t o1 = ob + (size_t)ch1 * POOL * POOL + pw1;

    if (ys > ye) {                        // fully zero-padded row bin -> 0
        out[o0] = 0.0f;
        if (r1) out[o1] = 0.0f;
        return;
    }

    int px2 = px & ~1;                    // even-aligned load base
    int dpx = px - px2;                   // 0 or 1
    bool act = (px2 + 2 * lane) <= qx;    // this lane's float2 needed?

    const float2* p = (const float2*)(feat
        + (size_t)(b * C + cg * CH) * H * W + (py + ys) * W + px2) + lane;
    const int PL2 = H * W / 2;            // plane stride in float2

    float2 a0 = make_float2(-INFINITY, -INFINITY);
    float2 a1 = a0, a2 = a0, a3 = a0, a4 = a0, a5 = a0, a6 = a0, a7 = a0;

#define FM2(d, s) d.x = fmaxf(d.x, s.x); d.y = fmaxf(d.y, s.y)
    for (int ry = ys; ry <= ye; ++ry) {   // 8 LDG.64 in flight per row
        if (act) {
            float2 v0 = __ldg(p);
            float2 v1 = __ldg(p + PL2);
            float2 v2 = __ldg(p + 2 * PL2);
            float2 v3 = __ldg(p + 3 * PL2);
            float2 v4 = __ldg(p + 4 * PL2);
            float2 v5 = __ldg(p + 5 * PL2);
            float2 v6 = __ldg(p + 6 * PL2);
            float2 v7 = __ldg(p + 7 * PL2);
            FM2(a0, v0); FM2(a1, v1); FM2(a2, v2); FM2(a3, v3);
            FM2(a4, v4); FM2(a5, v5); FM2(a6, v6); FM2(a7, v7);
        }
        p += W / 2;
    }
#undef FM2

    // flush column maxima
    float* cw = cm[warp];
    int si = 2 * lane;
    *(float2*)(cw + 0 * CMW + si) = a0;
    *(float2*)(cw + 1 * CMW + si) = a1;
    *(float2*)(cw + 2 * CMW + si) = a2;
    *(float2*)(cw + 3 * CMW + si) = a3;
    *(float2*)(cw + 4 * CMW + si) = a4;
    *(float2*)(cw + 5 * CMW + si) = a5;
    *(float2*)(cw + 6 * CMW + si) = a6;
    *(float2*)(cw + 7 * CMW + si) = a7;
    __syncwarp();

    bool pady = (ph * psy < pad0y) | ((ph + 1) * psy > pad0y + leny);

    // x-direction segmented max for the lane's two bins
    {
        int x0 = pw0 * psx - pad0x;
        int i0 = max(0, -x0);
        int i1 = min(psx, lenx - x0);
        const float* rp = cw + ch0 * CMW + x0 + dpx;
        float mm = -INFINITY;
        for (int i = i0; i < i1; ++i) mm = fmaxf(mm, rp[i]);
        bool padx = (pw0 * psx < pad0x) | ((pw0 + 1) * psx > pad0x + lenx);
        if (padx | pady) mm = fmaxf(mm, 0.0f);
        if (!isfinite(mm)) mm = 0.0f;     // fully-padded bin -> 0
        out[o0] = mm;
    }
    if (r1) {
        int x0 = pw1 * psx - pad0x;
        int i0 = max(0, -x0);
        int i1 = min(psx, lenx - x0);
        const float* rp = cw + ch1 * CMW + x0 + dpx;
        float mm = -INFINITY;
        for (int i = i0; i < i1; ++i) mm = fmaxf(mm, rp[i]);
        bool padx = (pw1 * psx < pad0x) | ((pw1 + 1) * psx > pad0x + lenx);
        if (padx | pady) mm = fmaxf(mm, 0.0f);
        if (!isfinite(mm)) mm = 0.0f;
        out[o1] = mm;
    }
}

extern "C" void kernel_launch(void* const* d_in, const int* in_sizes, int n_in,
                              void* d_out, int out_size) {
    const float* feat = (const float*)d_in[0];
    const float* rois = (const float*)d_in[1];
    float* out = (float*)d_out;

    const int C = 256;
    int N = in_sizes[1] / 5;

    int total = N * C * POOL * POOL;
    int write_bid = (out_size >= total + N) ? 1 : 0;

    dim3 grid(TPR / WPB, N);              // 28 x N blocks
    roipool_kernel<<<grid, 32 * WPB>>>(feat, rois, out, N, C, write_bid);
}